// round 7
// baseline (speedup 1.0000x reference)
#include <cuda_runtime.h>
#include <cuda_bf16.h>
#include <cstdint>

// Problem constants (shapes are fixed by the dataset)
#define NN 100000
#define EE 1600000
#define DH 128
#define NG 1024

// ---------------- device scratch (no allocations allowed) ----------------
__device__ float d_bufA[(size_t)NN * DH];   // 51.2 MB
__device__ float d_bufB[(size_t)NN * DH];   // 51.2 MB
__device__ int   d_deg[NN];
__device__ float d_dinv[NN];
__device__ int   d_rowptr[NN];
__device__ int   d_cursor[NN];
__device__ int   d_csrc[EE];                // CSR: src node per incoming edge
__device__ int   d_src32[EE];
__device__ int   d_dst32[EE];
__device__ int   d_batch32[NN];
__device__ float d_gsum[2 * NG];
__device__ int   d_gcnt[NG];
__device__ int   d_is64;                    // 1 if indices are int64, 0 if int32

// Buffer selector: resolve scratch buffers INSIDE device code (always legal).
template <int SEL>
__device__ __forceinline__ float* buf_ptr(const float* ext) {
    if (SEL == 1) return &d_bufA[0];
    if (SEL == 2) return &d_bufB[0];
    return (float*)ext;
}

// ---------------- f32x2 packed FMA helpers ----------------
__device__ __forceinline__ unsigned long long pk2(float lo, float hi) {
    unsigned long long r;
    asm("mov.b64 %0, {%1, %2};" : "=l"(r) : "f"(lo), "f"(hi));
    return r;
}
__device__ __forceinline__ void fma2(unsigned long long& d, unsigned long long a, unsigned long long b) {
    asm("fma.rn.f32x2 %0, %1, %2, %0;" : "+l"(d) : "l"(a), "l"(b));
}
__device__ __forceinline__ float2 upk2(unsigned long long v) {
    float2 f;
    asm("mov.b64 {%0, %1}, %2;" : "=f"(f.x), "=f"(f.y) : "l"(v));
    return f;
}

// ---------------- dtype detection: int64 vs int32 index data ----------------
// Reads the first few entries as int64; int32 data read as int64 fuses two
// node ids -> values >= NN with overwhelming probability.
__global__ void detect_kernel(const void* __restrict__ ei, int twoE) {
    __shared__ int bad;
    if (threadIdx.x == 0) bad = 0;
    __syncthreads();
    const long long* p64 = (const long long*)ei;
    int lim = twoE / 2;          // safe int64 slots even if data is int32
    if (lim > 512) lim = 512;
    for (int i = threadIdx.x; i < lim; i += blockDim.x) {
        long long v = p64[i];
        if (v < 0 || v >= NN) atomicOr(&bad, 1);
    }
    __syncthreads();
    if (threadIdx.x == 0) d_is64 = bad ? 0 : 1;
}

// ---------------- convert edges to int32 (clamped) ----------------
__global__ void convert_edges_kernel(const void* __restrict__ ei, int E) {
    int e = blockIdx.x * blockDim.x + threadIdx.x;
    if (e >= E) return;
    int s, d;
    if (d_is64) {
        const long long* p = (const long long*)ei;
        s = (int)p[e];
        d = (int)p[(size_t)E + e];
    } else {
        const int* p = (const int*)ei;
        s = p[e];
        d = p[E + e];
    }
    s = min(max(s, 0), NN - 1);
    d = min(max(d, 0), NN - 1);
    d_src32[e] = s;
    d_dst32[e] = d;
}

// ---------------- convert batch to int32 (clamped) ----------------
__global__ void convert_batch_kernel(const void* __restrict__ batch, int n) {
    int i = blockIdx.x * blockDim.x + threadIdx.x;
    if (i >= n) return;
    int g;
    if (d_is64) g = (int)((const long long*)batch)[i];
    else        g = ((const int*)batch)[i];
    d_batch32[i] = min(max(g, 0), NG - 1);
}

// ---------------- zero scratch accumulators ----------------
__global__ void zero_kernel(int n) {
    int i = blockIdx.x * blockDim.x + threadIdx.x;
    if (i < n) d_deg[i] = 0;
    if (i < 2 * NG) d_gsum[i] = 0.f;
    if (i < NG) d_gcnt[i] = 0;
}

// ---------------- degree count (in-degree over dst) ----------------
__global__ void count_deg_kernel(int E) {
    int e = blockIdx.x * blockDim.x + threadIdx.x;
    if (e < E) atomicAdd(&d_deg[d_dst32[e]], 1);
}

// ---------------- graph-id counts ----------------
__global__ void count_graph_kernel(int n) {
    int i = blockIdx.x * blockDim.x + threadIdx.x;
    if (i < n) atomicAdd(&d_gcnt[d_batch32[i]], 1);
}

// ---------------- dinv = rsqrt(in-degree + 1 self loop) ----------------
__global__ void dinv_kernel(int n) {
    int i = blockIdx.x * blockDim.x + threadIdx.x;
    if (i < n) d_dinv[i] = rsqrtf((float)(d_deg[i] + 1));
}

// ---------------- single-block exclusive scan over d_deg ----------------
__global__ void scan_kernel(int n) {
    __shared__ int wsum[32];
    int tid = threadIdx.x;
    int L = (n + 1023) >> 10;
    int beg = tid * L;
    int end = min(beg + L, n);
    int s = 0;
    for (int i = beg; i < end; i++) s += d_deg[i];
    int lane = tid & 31, wid = tid >> 5;
    int v = s;
#pragma unroll
    for (int o = 1; o < 32; o <<= 1) {
        int t = __shfl_up_sync(0xffffffffu, v, o);
        if (lane >= o) v += t;
    }
    if (lane == 31) wsum[wid] = v;
    __syncthreads();
    if (wid == 0) {
        int w = wsum[lane];
#pragma unroll
        for (int o = 1; o < 32; o <<= 1) {
            int t = __shfl_up_sync(0xffffffffu, w, o);
            if (lane >= o) w += t;
        }
        wsum[lane] = w;
    }
    __syncthreads();
    int run = (wid > 0 ? wsum[wid - 1] : 0) + (v - s);
    for (int i = beg; i < end; i++) {
        int dv = d_deg[i];
        d_rowptr[i] = run;
        d_cursor[i] = run;
        run += dv;
    }
}

// ---------------- CSR fill (counting sort by dst) ----------------
__global__ void fill_kernel(int E) {
    int e = blockIdx.x * blockDim.x + threadIdx.x;
    if (e < E) {
        int dst = d_dst32[e];
        int p = atomicAdd(&d_cursor[dst], 1);
        d_csrc[p] = d_src32[e];
    }
}

// ---------------- 128x128 GEMM: Y[n,128] = X[n,128] @ W[128,128] ----------------
#define BM 64
#define XS_PITCH 132
template <int SRC, int DST>
__global__ __launch_bounds__(256) void gemm128_kernel(const float* __restrict__ Xext,
                                                      const float* __restrict__ W,
                                                      int n) {
    const float* X = buf_ptr<SRC>(Xext);
    float* Y = buf_ptr<DST>(nullptr);

    extern __shared__ float smem[];
    float* ws = smem;                 // 128*128 floats
    float* xs = smem + 128 * 128;     // BM * XS_PITCH floats

    int tid = threadIdx.x;
    int row0 = blockIdx.x * BM;

    for (int i = tid * 4; i < 128 * 128; i += 256 * 4) {
        *(float4*)(ws + i) = *(const float4*)(W + i);
    }
    {
        int r = tid >> 5;
        int c4 = tid & 31;
        for (int rr = r; rr < BM; rr += 8) {
            int gr = row0 + rr;
            float4 v = make_float4(0.f, 0.f, 0.f, 0.f);
            if (gr < n) v = *(const float4*)(X + (size_t)gr * 128 + c4 * 4);
            *(float4*)(xs + rr * XS_PITCH + c4 * 4) = v;
        }
    }
    __syncthreads();

    int tx = tid & 15, ty = tid >> 4;
    int c0 = tx * 8, n0 = ty * 4;

    unsigned long long acc[4][4];
#pragma unroll
    for (int i = 0; i < 4; i++)
#pragma unroll
        for (int j = 0; j < 4; j++) acc[i][j] = 0ull;

    for (int k4 = 0; k4 < 128; k4 += 4) {
        float4 a[4];
#pragma unroll
        for (int i = 0; i < 4; i++) a[i] = *(const float4*)(xs + (n0 + i) * XS_PITCH + k4);
#pragma unroll
        for (int kk = 0; kk < 4; kk++) {
            int k = k4 + kk;
            float4 w0 = *(const float4*)(ws + k * 128 + c0);
            float4 w1 = *(const float4*)(ws + k * 128 + c0 + 4);
            unsigned long long wp0 = pk2(w0.x, w0.y);
            unsigned long long wp1 = pk2(w0.z, w0.w);
            unsigned long long wp2 = pk2(w1.x, w1.y);
            unsigned long long wp3 = pk2(w1.z, w1.w);
#pragma unroll
            for (int i = 0; i < 4; i++) {
                float av = (kk == 0) ? a[i].x : (kk == 1) ? a[i].y : (kk == 2) ? a[i].z : a[i].w;
                unsigned long long a2 = pk2(av, av);
                fma2(acc[i][0], a2, wp0);
                fma2(acc[i][1], a2, wp1);
                fma2(acc[i][2], a2, wp2);
                fma2(acc[i][3], a2, wp3);
            }
        }
    }

#pragma unroll
    for (int i = 0; i < 4; i++) {
        int gr = row0 + n0 + i;
        if (gr < n) {
            float2 r0 = upk2(acc[i][0]), r1 = upk2(acc[i][1]);
            float2 r2 = upk2(acc[i][2]), r3 = upk2(acc[i][3]);
            float4 o0 = make_float4(r0.x, r0.y, r1.x, r1.y);
            float4 o1 = make_float4(r2.x, r2.y, r3.x, r3.y);
            *(float4*)(Y + (size_t)gr * 128 + c0) = o0;
            *(float4*)(Y + (size_t)gr * 128 + c0 + 4) = o1;
        }
    }
}

// ---------------- aggregation: warp per node, CSR gather, relu+bias ----------------
template <int SRC, int DST>
__global__ __launch_bounds__(256) void agg_kernel(const float* __restrict__ bias, int n) {
    const float* h = buf_ptr<SRC>(nullptr);
    float* out = buf_ptr<DST>(nullptr);

    int w = (blockIdx.x * blockDim.x + threadIdx.x) >> 5;
    int lane = threadIdx.x & 31;
    if (w >= n) return;
    int start = d_rowptr[w];
    int d = d_deg[w];
    float4 acc = make_float4(0.f, 0.f, 0.f, 0.f);
    int i = 0;
    for (; i + 2 <= d; i += 2) {
        int s0 = d_csrc[start + i];
        int s1 = d_csrc[start + i + 1];
        float w0 = d_dinv[s0];
        float w1 = d_dinv[s1];
        float4 h0 = *(const float4*)(h + (size_t)s0 * 128 + lane * 4);
        float4 h1 = *(const float4*)(h + (size_t)s1 * 128 + lane * 4);
        acc.x = fmaf(w0, h0.x, fmaf(w1, h1.x, acc.x));
        acc.y = fmaf(w0, h0.y, fmaf(w1, h1.y, acc.y));
        acc.z = fmaf(w0, h0.z, fmaf(w1, h1.z, acc.z));
        acc.w = fmaf(w0, h0.w, fmaf(w1, h1.w, acc.w));
    }
    if (i < d) {
        int s0 = d_csrc[start + i];
        float w0 = d_dinv[s0];
        float4 h0 = *(const float4*)(h + (size_t)s0 * 128 + lane * 4);
        acc.x = fmaf(w0, h0.x, acc.x);
        acc.y = fmaf(w0, h0.y, acc.y);
        acc.z = fmaf(w0, h0.z, acc.z);
        acc.w = fmaf(w0, h0.w, acc.w);
    }
    float dv = d_dinv[w];
    float4 hs = *(const float4*)(h + (size_t)w * 128 + lane * 4);
    acc.x = fmaf(dv, hs.x, acc.x);
    acc.y = fmaf(dv, hs.y, acc.y);
    acc.z = fmaf(dv, hs.z, acc.z);
    acc.w = fmaf(dv, hs.w, acc.w);
    float4 bv = *(const float4*)(bias + lane * 4);
    float4 o;
    o.x = fmaxf(fmaf(dv, acc.x, bv.x), 0.f);
    o.y = fmaxf(fmaf(dv, acc.y, bv.y), 0.f);
    o.z = fmaxf(fmaf(dv, acc.z, bv.z), 0.f);
    o.w = fmaxf(fmaf(dv, acc.w, bv.w), 0.f);
    *(float4*)(out + (size_t)w * 128 + lane * 4) = o;
}

// ---------------- per-node classifier dot (128 -> 2), atomic sums per graph ----------
template <int SRC>
__global__ __launch_bounds__(256) void classify_kernel(const float* __restrict__ Wc, int n) {
    const float* h = buf_ptr<SRC>(nullptr);
    int w = (blockIdx.x * blockDim.x + threadIdx.x) >> 5;
    int lane = threadIdx.x & 31;
    if (w >= n) return;
    float4 hv = *(const float4*)(h + (size_t)w * 128 + lane * 4);
    float4 wa = *(const float4*)(Wc + 8 * lane);
    float4 wb = *(const float4*)(Wc + 8 * lane + 4);
    float p0 = hv.x * wa.x + hv.y * wa.z + hv.z * wb.x + hv.w * wb.z;
    float p1 = hv.x * wa.y + hv.y * wa.w + hv.z * wb.y + hv.w * wb.w;
#pragma unroll
    for (int o = 16; o; o >>= 1) {
        p0 += __shfl_xor_sync(0xffffffffu, p0, o);
        p1 += __shfl_xor_sync(0xffffffffu, p1, o);
    }
    if (lane == 0) {
        int g = d_batch32[w];
        atomicAdd(&d_gsum[2 * g], p0);
        atomicAdd(&d_gsum[2 * g + 1], p1);
    }
}

// ---------------- finalize: mean + bias ----------------
__global__ void finalize_kernel(float* __restrict__ out, const float* __restrict__ bc, int G) {
    int i = blockIdx.x * blockDim.x + threadIdx.x;
    if (i < 2 * G) {
        int g = i >> 1, c = i & 1;
        float cnt = (float)d_gcnt[g];
        out[i] = d_gsum[i] / fmaxf(cnt, 1.f) + bc[c];
    }
}

// ---------------- launch ----------------
extern "C" void kernel_launch(void* const* d_in, const int* in_sizes, int n_in,
                              void* d_out, int out_size) {
    // Identify inputs by element count (robust to metadata ordering):
    //   x: N*128 (largest), edge_index: 2E (millions), batch: N,
    //   W1/W2: 16384 (appearance order), b1/b2: 128 (appearance order),
    //   Wc: 256, bc: 2.
    const float* x = nullptr;
    const void* ei = nullptr;
    const void* batch = nullptr;
    const float *W1 = nullptr, *b1 = nullptr, *W2 = nullptr, *b2 = nullptr;
    const float *Wc = nullptr, *bc = nullptr;
    int x_elems = 0, ei_elems = 0;

    for (int i = 0; i < n_in; i++) {
        int s = in_sizes[i];
        const void* p = d_in[i];
        if (s >= 8000000)      { x = (const float*)p; x_elems = s; }
        else if (s >= 1000000) { ei = p; ei_elems = s; }
        else if (s == NN)      { batch = p; }
        else if (s == DH * DH) { if (!W1) W1 = (const float*)p; else W2 = (const float*)p; }
        else if (s == DH)      { if (!b1) b1 = (const float*)p; else b2 = (const float*)p; }
        else if (s == 2 * DH)  { Wc = (const float*)p; }
        else if (s == 2)       { bc = (const float*)p; }
    }

    float* out = (float*)d_out;
    int N = x_elems / DH;
    int E = ei_elems / 2;
    int G = out_size / 2;

    const int T = 256;
    int gemm_smem = 128 * 128 * 4 + BM * XS_PITCH * 4;
    cudaFuncSetAttribute(gemm128_kernel<0, 1>, cudaFuncAttributeMaxDynamicSharedMemorySize, gemm_smem);
    cudaFuncSetAttribute(gemm128_kernel<2, 1>, cudaFuncAttributeMaxDynamicSharedMemorySize, gemm_smem);

    // Build phase
    detect_kernel<<<1, 256>>>(ei, 2 * E);
    zero_kernel<<<(N + T - 1) / T, T>>>(N);
    convert_edges_kernel<<<(E + T - 1) / T, T>>>(ei, E);
    convert_batch_kernel<<<(N + T - 1) / T, T>>>(batch, N);
    count_deg_kernel<<<(E + T - 1) / T, T>>>(E);
    count_graph_kernel<<<(N + T - 1) / T, T>>>(N);
    dinv_kernel<<<(N + T - 1) / T, T>>>(N);
    scan_kernel<<<1, 1024>>>(N);
    fill_kernel<<<(E + T - 1) / T, T>>>(E);

    int gemm_blocks = (N + BM - 1) / BM;
    int agg_blocks = (N + 7) / 8;

    // Layer 1: x -> bufA (gemm), bufA -> bufB (agg)
    gemm128_kernel<0, 1><<<gemm_blocks, T, gemm_smem>>>(x, W1, N);
    agg_kernel<1, 2><<<agg_blocks, T>>>(b1, N);
    // Layer 2: bufB -> bufA (gemm), bufA -> bufB (agg)
    gemm128_kernel<2, 1><<<gemm_blocks, T, gemm_smem>>>(nullptr, W2, N);
    agg_kernel<1, 2><<<agg_blocks, T>>>(b2, N);

    // Classifier folded through the mean pool
    classify_kernel<2><<<agg_blocks, T>>>(Wc, N);
    finalize_kernel<<<(2 * G + T - 1) / T, T>>>(out, bc, G);
}

// round 9
// speedup vs baseline: 1.0100x; 1.0100x over previous
#include <cuda_runtime.h>
#include <cuda_bf16.h>
#include <cstdint>

// Problem constants (shapes are fixed by the dataset)
#define NN 100000
#define EE 1600000
#define DH 128
#define NG 1024

// ---------------- device scratch (no allocations allowed) ----------------
__device__ float d_bufA[(size_t)NN * DH];   // 51.2 MB
__device__ float d_bufB[(size_t)NN * DH];   // 51.2 MB
__device__ int   d_deg[NN];
__device__ float d_dinv[NN];
__device__ int   d_rowptr[NN];
__device__ int   d_cursor[NN];
__device__ int2  d_csw[EE];                 // CSR: (src, bits(dinv[src])) per incoming edge
__device__ int   d_src32[EE];
__device__ int   d_dst32[EE];
__device__ int   d_batch32[NN];
__device__ float d_gsum[2 * NG];
__device__ int   d_gcnt[NG];
__device__ int   d_is64;                    // 1 if indices are int64, 0 if int32

// Buffer selector: resolve scratch buffers INSIDE device code (always legal).
template <int SEL>
__device__ __forceinline__ float* buf_ptr(const float* ext) {
    if (SEL == 1) return &d_bufA[0];
    if (SEL == 2) return &d_bufB[0];
    return (float*)ext;
}

// ---------------- f32x2 packed FMA helpers ----------------
__device__ __forceinline__ unsigned long long pk2(float lo, float hi) {
    unsigned long long r;
    asm("mov.b64 %0, {%1, %2};" : "=l"(r) : "f"(lo), "f"(hi));
    return r;
}
__device__ __forceinline__ void fma2(unsigned long long& d, unsigned long long a, unsigned long long b) {
    asm("fma.rn.f32x2 %0, %1, %2, %0;" : "+l"(d) : "l"(a), "l"(b));
}
__device__ __forceinline__ float2 upk2(unsigned long long v) {
    float2 f;
    asm("mov.b64 {%0, %1}, %2;" : "=f"(f.x), "=f"(f.y) : "l"(v));
    return f;
}

// ---------------- dtype detection: int64 vs int32 index data ----------------
__global__ void detect_kernel(const void* __restrict__ ei, int twoE) {
    __shared__ int bad;
    if (threadIdx.x == 0) bad = 0;
    __syncthreads();
    const long long* p64 = (const long long*)ei;
    int lim = twoE / 2;
    if (lim > 512) lim = 512;
    for (int i = threadIdx.x; i < lim; i += blockDim.x) {
        long long v = p64[i];
        if (v < 0 || v >= NN) atomicOr(&bad, 1);
    }
    __syncthreads();
    if (threadIdx.x == 0) d_is64 = bad ? 0 : 1;
}

// ---------------- zero scratch accumulators ----------------
__global__ void zero_kernel(int n) {
    int i = blockIdx.x * blockDim.x + threadIdx.x;
    if (i < n) d_deg[i] = 0;
    if (i < 2 * NG) d_gsum[i] = 0.f;
    if (i < NG) d_gcnt[i] = 0;
}

// ---------------- convert edges to int32 (clamped) + in-degree count ----------------
__global__ void convert_edges_kernel(const void* __restrict__ ei, int E) {
    int e = blockIdx.x * blockDim.x + threadIdx.x;
    if (e >= E) return;
    int s, d;
    if (d_is64) {
        const long long* p = (const long long*)ei;
        s = (int)p[e];
        d = (int)p[(size_t)E + e];
    } else {
        const int* p = (const int*)ei;
        s = p[e];
        d = p[E + e];
    }
    s = min(max(s, 0), NN - 1);
    d = min(max(d, 0), NN - 1);
    d_src32[e] = s;
    d_dst32[e] = d;
    atomicAdd(&d_deg[d], 1);
}

// ---------------- convert batch to int32 (clamped) + graph count ----------------
__global__ void convert_batch_kernel(const void* __restrict__ batch, int n) {
    int i = blockIdx.x * blockDim.x + threadIdx.x;
    if (i >= n) return;
    int g;
    if (d_is64) g = (int)((const long long*)batch)[i];
    else        g = ((const int*)batch)[i];
    g = min(max(g, 0), NG - 1);
    d_batch32[i] = g;
    atomicAdd(&d_gcnt[g], 1);
}

// ---------------- dinv = rsqrt(in-degree + 1 self loop) ----------------
__global__ void dinv_kernel(int n) {
    int i = blockIdx.x * blockDim.x + threadIdx.x;
    if (i < n) d_dinv[i] = rsqrtf((float)(d_deg[i] + 1));
}

// ---------------- single-block exclusive scan over d_deg ----------------
__global__ void scan_kernel(int n) {
    __shared__ int wsum[32];
    int tid = threadIdx.x;
    int L = (n + 1023) >> 10;
    int beg = tid * L;
    int end = min(beg + L, n);
    int s = 0;
    for (int i = beg; i < end; i++) s += d_deg[i];
    int lane = tid & 31, wid = tid >> 5;
    int v = s;
#pragma unroll
    for (int o = 1; o < 32; o <<= 1) {
        int t = __shfl_up_sync(0xffffffffu, v, o);
        if (lane >= o) v += t;
    }
    if (lane == 31) wsum[wid] = v;
    __syncthreads();
    if (wid == 0) {
        int w = wsum[lane];
#pragma unroll
        for (int o = 1; o < 32; o <<= 1) {
            int t = __shfl_up_sync(0xffffffffu, w, o);
            if (lane >= o) w += t;
        }
        wsum[lane] = w;
    }
    __syncthreads();
    int run = (wid > 0 ? wsum[wid - 1] : 0) + (v - s);
    for (int i = beg; i < end; i++) {
        int dv = d_deg[i];
        d_rowptr[i] = run;
        d_cursor[i] = run;
        run += dv;
    }
}

// ---------------- CSR fill: (src, dinv[src]) pairs, counting sort by dst ----------
__global__ void fill_kernel(int E) {
    int e = blockIdx.x * blockDim.x + threadIdx.x;
    if (e < E) {
        int src = d_src32[e];
        int dst = d_dst32[e];
        int p = atomicAdd(&d_cursor[dst], 1);
        d_csw[p] = make_int2(src, __float_as_int(d_dinv[src]));
    }
}

// ---------------- 128x128 GEMM: Y[n,128] = X[n,128] @ W[128,128] ----------------
#define BM 64
#define XS_PITCH 132
template <int SRC, int DST>
__global__ __launch_bounds__(256) void gemm128_kernel(const float* __restrict__ Xext,
                                                      const float* __restrict__ W,
                                                      int n) {
    const float* X = buf_ptr<SRC>(Xext);
    float* Y = buf_ptr<DST>(nullptr);

    extern __shared__ float smem[];
    float* ws = smem;                 // 128*128 floats
    float* xs = smem + 128 * 128;     // BM * XS_PITCH floats

    int tid = threadIdx.x;
    int row0 = blockIdx.x * BM;

    for (int i = tid * 4; i < 128 * 128; i += 256 * 4) {
        *(float4*)(ws + i) = *(const float4*)(W + i);
    }
    {
        int r = tid >> 5;
        int c4 = tid & 31;
        for (int rr = r; rr < BM; rr += 8) {
            int gr = row0 + rr;
            float4 v = make_float4(0.f, 0.f, 0.f, 0.f);
            if (gr < n) v = *(const float4*)(X + (size_t)gr * 128 + c4 * 4);
            *(float4*)(xs + rr * XS_PITCH + c4 * 4) = v;
        }
    }
    __syncthreads();

    int tx = tid & 15, ty = tid >> 4;
    int c0 = tx * 8, n0 = ty * 4;

    unsigned long long acc[4][4];
#pragma unroll
    for (int i = 0; i < 4; i++)
#pragma unroll
        for (int j = 0; j < 4; j++) acc[i][j] = 0ull;

    for (int k4 = 0; k4 < 128; k4 += 4) {
        float4 a[4];
#pragma unroll
        for (int i = 0; i < 4; i++) a[i] = *(const float4*)(xs + (n0 + i) * XS_PITCH + k4);
#pragma unroll
        for (int kk = 0; kk < 4; kk++) {
            int k = k4 + kk;
            float4 w0 = *(const float4*)(ws + k * 128 + c0);
            float4 w1 = *(const float4*)(ws + k * 128 + c0 + 4);
            unsigned long long wp0 = pk2(w0.x, w0.y);
            unsigned long long wp1 = pk2(w0.z, w0.w);
            unsigned long long wp2 = pk2(w1.x, w1.y);
            unsigned long long wp3 = pk2(w1.z, w1.w);
#pragma unroll
            for (int i = 0; i < 4; i++) {
                float av = (kk == 0) ? a[i].x : (kk == 1) ? a[i].y : (kk == 2) ? a[i].z : a[i].w;
                unsigned long long a2 = pk2(av, av);
                fma2(acc[i][0], a2, wp0);
                fma2(acc[i][1], a2, wp1);
                fma2(acc[i][2], a2, wp2);
                fma2(acc[i][3], a2, wp3);
            }
        }
    }

#pragma unroll
    for (int i = 0; i < 4; i++) {
        int gr = row0 + n0 + i;
        if (gr < n) {
            float2 r0 = upk2(acc[i][0]), r1 = upk2(acc[i][1]);
            float2 r2 = upk2(acc[i][2]), r3 = upk2(acc[i][3]);
            float4 o0 = make_float4(r0.x, r0.y, r1.x, r1.y);
            float4 o1 = make_float4(r2.x, r2.y, r3.x, r3.y);
            *(float4*)(Y + (size_t)gr * 128 + c0) = o0;
            *(float4*)(Y + (size_t)gr * 128 + c0 + 4) = o1;
        }
    }
}

// ---------------- aggregation: warp per node, CSR gather, relu+bias ----------------
// Unrolled x4 with front-batched loads: 4 broadcast int2 (src,weight) loads, then
// 4 independent float4 row gathers -> MLP ~4, no dependent dinv gather.
template <int SRC, int DST>
__global__ __launch_bounds__(256) void agg_kernel(const float* __restrict__ bias, int n) {
    const float* h = buf_ptr<SRC>(nullptr);
    float* out = buf_ptr<DST>(nullptr);

    int w = (blockIdx.x * blockDim.x + threadIdx.x) >> 5;
    int lane = threadIdx.x & 31;
    if (w >= n) return;
    int start = d_rowptr[w];
    int d = d_deg[w];
    int end = start + d;

    float4 acc = make_float4(0.f, 0.f, 0.f, 0.f);
    int i = start;
    for (; i + 4 <= end; i += 4) {
        int2 p0 = d_csw[i];
        int2 p1 = d_csw[i + 1];
        int2 p2 = d_csw[i + 2];
        int2 p3 = d_csw[i + 3];
        float4 h0 = *(const float4*)(h + (size_t)p0.x * 128 + lane * 4);
        float4 h1 = *(const float4*)(h + (size_t)p1.x * 128 + lane * 4);
        float4 h2 = *(const float4*)(h + (size_t)p2.x * 128 + lane * 4);
        float4 h3 = *(const float4*)(h + (size_t)p3.x * 128 + lane * 4);
        float w0 = __int_as_float(p0.y), w1 = __int_as_float(p1.y);
        float w2 = __int_as_float(p2.y), w3 = __int_as_float(p3.y);
        acc.x = fmaf(w0, h0.x, acc.x); acc.y = fmaf(w0, h0.y, acc.y);
        acc.z = fmaf(w0, h0.z, acc.z); acc.w = fmaf(w0, h0.w, acc.w);
        acc.x = fmaf(w1, h1.x, acc.x); acc.y = fmaf(w1, h1.y, acc.y);
        acc.z = fmaf(w1, h1.z, acc.z); acc.w = fmaf(w1, h1.w, acc.w);
        acc.x = fmaf(w2, h2.x, acc.x); acc.y = fmaf(w2, h2.y, acc.y);
        acc.z = fmaf(w2, h2.z, acc.z); acc.w = fmaf(w2, h2.w, acc.w);
        acc.x = fmaf(w3, h3.x, acc.x); acc.y = fmaf(w3, h3.y, acc.y);
        acc.z = fmaf(w3, h3.z, acc.z); acc.w = fmaf(w3, h3.w, acc.w);
    }
    for (; i < end; i++) {
        int2 p0 = d_csw[i];
        float w0 = __int_as_float(p0.y);
        float4 h0 = *(const float4*)(h + (size_t)p0.x * 128 + lane * 4);
        acc.x = fmaf(w0, h0.x, acc.x);
        acc.y = fmaf(w0, h0.y, acc.y);
        acc.z = fmaf(w0, h0.z, acc.z);
        acc.w = fmaf(w0, h0.w, acc.w);
    }
    float dv = d_dinv[w];
    float4 hs = *(const float4*)(h + (size_t)w * 128 + lane * 4);
    acc.x = fmaf(dv, hs.x, acc.x);
    acc.y = fmaf(dv, hs.y, acc.y);
    acc.z = fmaf(dv, hs.z, acc.z);
    acc.w = fmaf(dv, hs.w, acc.w);
    float4 bv = *(const float4*)(bias + lane * 4);
    float4 o;
    o.x = fmaxf(fmaf(dv, acc.x, bv.x), 0.f);
    o.y = fmaxf(fmaf(dv, acc.y, bv.y), 0.f);
    o.z = fmaxf(fmaf(dv, acc.z, bv.z), 0.f);
    o.w = fmaxf(fmaf(dv, acc.w, bv.w), 0.f);
    *(float4*)(out + (size_t)w * 128 + lane * 4) = o;
}

// ---------------- per-node classifier dot (128 -> 2), atomic sums per graph ----------
template <int SRC>
__global__ __launch_bounds__(256) void classify_kernel(const float* __restrict__ Wc, int n) {
    const float* h = buf_ptr<SRC>(nullptr);
    int w = (blockIdx.x * blockDim.x + threadIdx.x) >> 5;
    int lane = threadIdx.x & 31;
    if (w >= n) return;
    float4 hv = *(const float4*)(h + (size_t)w * 128 + lane * 4);
    float4 wa = *(const float4*)(Wc + 8 * lane);
    float4 wb = *(const float4*)(Wc + 8 * lane + 4);
    float p0 = hv.x * wa.x + hv.y * wa.z + hv.z * wb.x + hv.w * wb.z;
    float p1 = hv.x * wa.y + hv.y * wa.w + hv.z * wb.y + hv.w * wb.w;
#pragma unroll
    for (int o = 16; o; o >>= 1) {
        p0 += __shfl_xor_sync(0xffffffffu, p0, o);
        p1 += __shfl_xor_sync(0xffffffffu, p1, o);
    }
    if (lane == 0) {
        int g = d_batch32[w];
        atomicAdd(&d_gsum[2 * g], p0);
        atomicAdd(&d_gsum[2 * g + 1], p1);
    }
}

// ---------------- finalize: mean + bias ----------------
__global__ void finalize_kernel(float* __restrict__ out, const float* __restrict__ bc, int G) {
    int i = blockIdx.x * blockDim.x + threadIdx.x;
    if (i < 2 * G) {
        int g = i >> 1, c = i & 1;
        float cnt = (float)d_gcnt[g];
        out[i] = d_gsum[i] / fmaxf(cnt, 1.f) + bc[c];
    }
}

// ---------------- launch ----------------
extern "C" void kernel_launch(void* const* d_in, const int* in_sizes, int n_in,
                              void* d_out, int out_size) {
    // Identify inputs by element count (robust to metadata ordering).
    const float* x = nullptr;
    const void* ei = nullptr;
    const void* batch = nullptr;
    const float *W1 = nullptr, *b1 = nullptr, *W2 = nullptr, *b2 = nullptr;
    const float *Wc = nullptr, *bc = nullptr;
    int x_elems = 0, ei_elems = 0;

    for (int i = 0; i < n_in; i++) {
        int s = in_sizes[i];
        const void* p = d_in[i];
        if (s >= 8000000)      { x = (const float*)p; x_elems = s; }
        else if (s >= 1000000) { ei = p; ei_elems = s; }
        else if (s == NN)      { batch = p; }
        else if (s == DH * DH) { if (!W1) W1 = (const float*)p; else W2 = (const float*)p; }
        else if (s == DH)      { if (!b1) b1 = (const float*)p; else b2 = (const float*)p; }
        else if (s == 2 * DH)  { Wc = (const float*)p; }
        else if (s == 2)       { bc = (const float*)p; }
    }

    float* out = (float*)d_out;
    int N = x_elems / DH;
    int E = ei_elems / 2;
    int G = out_size / 2;

    const int T = 256;
    int gemm_smem = 128 * 128 * 4 + BM * XS_PITCH * 4;
    cudaFuncSetAttribute(gemm128_kernel<0, 1>, cudaFuncAttributeMaxDynamicSharedMemorySize, gemm_smem);
    cudaFuncSetAttribute(gemm128_kernel<2, 1>, cudaFuncAttributeMaxDynamicSharedMemorySize, gemm_smem);

    // Build phase
    detect_kernel<<<1, 256>>>(ei, 2 * E);
    zero_kernel<<<(N + T - 1) / T, T>>>(N);
    convert_edges_kernel<<<(E + T - 1) / T, T>>>(ei, E);   // also counts in-degree
    convert_batch_kernel<<<(N + T - 1) / T, T>>>(batch, N); // also counts graphs
    dinv_kernel<<<(N + T - 1) / T, T>>>(N);
    scan_kernel<<<1, 1024>>>(N);
    fill_kernel<<<(E + T - 1) / T, T>>>(E);                 // packs (src, dinv[src])

    int gemm_blocks = (N + BM - 1) / BM;
    int agg_blocks = (N + 7) / 8;

    // Layer 1: x -> bufA (gemm), bufA -> bufB (agg)
    gemm128_kernel<0, 1><<<gemm_blocks, T, gemm_smem>>>(x, W1, N);
    agg_kernel<1, 2><<<agg_blocks, T>>>(b1, N);
    // Layer 2: bufB -> bufA (gemm), bufA -> bufB (agg)
    gemm128_kernel<2, 1><<<gemm_blocks, T, gemm_smem>>>(nullptr, W2, N);
    agg_kernel<1, 2><<<agg_blocks, T>>>(b2, N);

    // Classifier folded through the mean pool
    classify_kernel<2><<<agg_blocks, T>>>(Wc, N);
    finalize_kernel<<<(2 * G + T - 1) / T, T>>>(out, bc, G);
}

// round 16
// speedup vs baseline: 1.0316x; 1.0214x over previous
#include <cuda_runtime.h>
#include <cuda_fp16.h>
#include <cstdint>

// Problem constants (shapes are fixed by the dataset)
#define NN 100000
#define EE 1600000
#define DH 128
#define NG 1024

// ---------------- device scratch (no allocations allowed) ----------------
__device__ float  d_bufF[(size_t)NN * DH];  // 51.2 MB fp32 (agg1 output / gemm2 input)
__device__ __half d_bufH[(size_t)NN * DH];  // 25.6 MB fp16 (gemm output / agg gather input)
__device__ int    d_deg[NN];
__device__ float  d_dinv[NN];
__device__ int    d_rowptr[NN];
__device__ int    d_cursor[NN];
__device__ int2   d_csw[EE];                // CSR: (src, bits(dinv[src]))
__device__ int    d_src32[EE];
__device__ int    d_dst32[EE];
__device__ int    d_batch32[NN];
__device__ float  d_gsum[2 * NG];
__device__ int    d_gcnt[NG];
__device__ int    d_is64;

// ---------------- f32x2 packed FMA helpers ----------------
__device__ __forceinline__ unsigned long long pk2(float lo, float hi) {
    unsigned long long r;
    asm("mov.b64 %0, {%1, %2};" : "=l"(r) : "f"(lo), "f"(hi));
    return r;
}
__device__ __forceinline__ void fma2(unsigned long long& d, unsigned long long a, unsigned long long b) {
    asm("fma.rn.f32x2 %0, %1, %2, %0;" : "+l"(d) : "l"(a), "l"(b));
}
__device__ __forceinline__ float2 upk2(unsigned long long v) {
    float2 f;
    asm("mov.b64 {%0, %1}, %2;" : "=f"(f.x), "=f"(f.y) : "l"(v));
    return f;
}

// ---------------- launch 0: zero accumulators + dtype detect (block 0) --------------
__global__ void init_kernel(const void* __restrict__ ei, int twoE, int n) {
    int i = blockIdx.x * blockDim.x + threadIdx.x;
    if (i < n) d_deg[i] = 0;
    if (i < 2 * NG) d_gsum[i] = 0.f;
    if (i < NG) d_gcnt[i] = 0;
    if (blockIdx.x == 0) {
        __shared__ int bad;
        if (threadIdx.x == 0) bad = 0;
        __syncthreads();
        const long long* p64 = (const long long*)ei;
        int lim = twoE / 2;
        if (lim > 512) lim = 512;
        for (int k = threadIdx.x; k < lim; k += blockDim.x) {
            long long v = p64[k];
            if (v < 0 || v >= NN) atomicOr(&bad, 1);
        }
        __syncthreads();
        if (threadIdx.x == 0) d_is64 = bad ? 0 : 1;
    }
}

// ---------------- launch 1: convert edges + batch, count degrees + graphs ----------
__global__ void convert_kernel(const void* __restrict__ ei, const void* __restrict__ batch,
                               int E, int n) {
    int i = blockIdx.x * blockDim.x + threadIdx.x;
    int is64 = d_is64;
    if (i < E) {
        int s, d;
        if (is64) {
            const long long* p = (const long long*)ei;
            s = (int)p[i];
            d = (int)p[(size_t)E + i];
        } else {
            const int* p = (const int*)ei;
            s = p[i];
            d = p[E + i];
        }
        s = min(max(s, 0), NN - 1);
        d = min(max(d, 0), NN - 1);
        d_src32[i] = s;
        d_dst32[i] = d;
        atomicAdd(&d_deg[d], 1);
    }
    if (i < n) {
        int g;
        if (is64) g = (int)((const long long*)batch)[i];
        else      g = ((const int*)batch)[i];
        g = min(max(g, 0), NG - 1);
        d_batch32[i] = g;
        atomicAdd(&d_gcnt[g], 1);
    }
}

// ---------------- launch 2: exclusive scan over d_deg + dinv ----------------
__global__ void scan_kernel(int n) {
    __shared__ int wsum[32];
    int tid = threadIdx.x;
    int L = (n + 1023) >> 10;
    int beg = tid * L;
    int end = min(beg + L, n);
    int s = 0;
    for (int i = beg; i < end; i++) s += d_deg[i];
    int lane = tid & 31, wid = tid >> 5;
    int v = s;
#pragma unroll
    for (int o = 1; o < 32; o <<= 1) {
        int t = __shfl_up_sync(0xffffffffu, v, o);
        if (lane >= o) v += t;
    }
    if (lane == 31) wsum[wid] = v;
    __syncthreads();
    if (wid == 0) {
        int w = wsum[lane];
#pragma unroll
        for (int o = 1; o < 32; o <<= 1) {
            int t = __shfl_up_sync(0xffffffffu, w, o);
            if (lane >= o) w += t;
        }
        wsum[lane] = w;
    }
    __syncthreads();
    int run = (wid > 0 ? wsum[wid - 1] : 0) + (v - s);
    for (int i = beg; i < end; i++) {
        int dv = d_deg[i];
        d_rowptr[i] = run;
        d_cursor[i] = run;
        d_dinv[i] = rsqrtf((float)(dv + 1));
        run += dv;
    }
}

// ---------------- launch 3: CSR fill (src, dinv[src]) pairs ----------------
__global__ void fill_kernel(int E) {
    int e = blockIdx.x * blockDim.x + threadIdx.x;
    if (e < E) {
        int src = d_src32[e];
        int dst = d_dst32[e];
        int p = atomicAdd(&d_cursor[dst], 1);
        d_csw[p] = make_int2(src, __float_as_int(d_dinv[src]));
    }
}

// ---------------- GEMM: H16[n,128] = X[n,128] @ W[128,128] (fp16 output) -----------
#define BM 64
#define XS_PITCH 132
template <int SRC>   // 0 = external fp32 pointer, 2 = d_bufF
__global__ __launch_bounds__(256) void gemm128_kernel(const float* __restrict__ Xext,
                                                      const float* __restrict__ W,
                                                      int n) {
    const float* X = (SRC == 2) ? &d_bufF[0] : Xext;
    __half* Y = &d_bufH[0];

    extern __shared__ float smem[];
    float* ws = smem;                 // 128*128 floats
    float* xs = smem + 128 * 128;     // BM * XS_PITCH floats

    int tid = threadIdx.x;
    int row0 = blockIdx.x * BM;

    for (int i = tid * 4; i < 128 * 128; i += 256 * 4) {
        *(float4*)(ws + i) = *(const float4*)(W + i);
    }
    {
        int r = tid >> 5;
        int c4 = tid & 31;
        for (int rr = r; rr < BM; rr += 8) {
            int gr = row0 + rr;
            float4 v = make_float4(0.f, 0.f, 0.f, 0.f);
            if (gr < n) v = *(const float4*)(X + (size_t)gr * 128 + c4 * 4);
            *(float4*)(xs + rr * XS_PITCH + c4 * 4) = v;
        }
    }
    __syncthreads();

    int tx = tid & 15, ty = tid >> 4;
    int c0 = tx * 8, n0 = ty * 4;

    unsigned long long acc[4][4];
#pragma unroll
    for (int i = 0; i < 4; i++)
#pragma unroll
        for (int j = 0; j < 4; j++) acc[i][j] = 0ull;

    for (int k4 = 0; k4 < 128; k4 += 4) {
        float4 a[4];
#pragma unroll
        for (int i = 0; i < 4; i++) a[i] = *(const float4*)(xs + (n0 + i) * XS_PITCH + k4);
#pragma unroll
        for (int kk = 0; kk < 4; kk++) {
            int k = k4 + kk;
            float4 w0 = *(const float4*)(ws + k * 128 + c0);
            float4 w1 = *(const float4*)(ws + k * 128 + c0 + 4);
            unsigned long long wp0 = pk2(w0.x, w0.y);
            unsigned long long wp1 = pk2(w0.z, w0.w);
            unsigned long long wp2 = pk2(w1.x, w1.y);
            unsigned long long wp3 = pk2(w1.z, w1.w);
#pragma unroll
            for (int i = 0; i < 4; i++) {
                float av = (kk == 0) ? a[i].x : (kk == 1) ? a[i].y : (kk == 2) ? a[i].z : a[i].w;
                unsigned long long a2 = pk2(av, av);
                fma2(acc[i][0], a2, wp0);
                fma2(acc[i][1], a2, wp1);
                fma2(acc[i][2], a2, wp2);
                fma2(acc[i][3], a2, wp3);
            }
        }
    }

#pragma unroll
    for (int i = 0; i < 4; i++) {
        int gr = row0 + n0 + i;
        if (gr < n) {
            float2 r0 = upk2(acc[i][0]), r1 = upk2(acc[i][1]);
            float2 r2 = upk2(acc[i][2]), r3 = upk2(acc[i][3]);
            __half2 h0 = __float22half2_rn(r0);
            __half2 h1 = __float22half2_rn(r1);
            __half2 h2 = __float22half2_rn(r2);
            __half2 h3 = __float22half2_rn(r3);
            uint4 ov;
            ov.x = *(unsigned int*)&h0;
            ov.y = *(unsigned int*)&h1;
            ov.z = *(unsigned int*)&h2;
            ov.w = *(unsigned int*)&h3;
            *(uint4*)((char*)Y + (size_t)gr * 256 + c0 * 2) = ov;
        }
    }
}

// ---------------- aggregation: warp/node, fp16 gathers, fp32 accum, relu+bias ------
// FUSE_CLASSIFY=false: write relu'd row to d_bufF (layer 1).
// FUSE_CLASSIFY=true : skip the store; compute the 128->2 classifier dot in-register
//                      and atomically add to d_gsum (layer 2 + classify fused).
template <bool FUSE_CLASSIFY>
__global__ __launch_bounds__(256) void agg_kernel(const float* __restrict__ bias,
                                                  const float* __restrict__ Wc, int n) {
    const __half* h = &d_bufH[0];
    float* out = &d_bufF[0];

    int w = (blockIdx.x * blockDim.x + threadIdx.x) >> 5;
    int lane = threadIdx.x & 31;
    if (w >= n) return;
    int start = d_rowptr[w];
    int d = d_deg[w];
    int end = start + d;

    float4 acc = make_float4(0.f, 0.f, 0.f, 0.f);
    int i = start;
    for (; i + 4 <= end; i += 4) {
        int2 p0 = d_csw[i];
        int2 p1 = d_csw[i + 1];
        int2 p2 = d_csw[i + 2];
        int2 p3 = d_csw[i + 3];
        uint2 r0 = *(const uint2*)((const char*)h + (size_t)p0.x * 256 + lane * 8);
        uint2 r1 = *(const uint2*)((const char*)h + (size_t)p1.x * 256 + lane * 8);
        uint2 r2 = *(const uint2*)((const char*)h + (size_t)p2.x * 256 + lane * 8);
        uint2 r3 = *(const uint2*)((const char*)h + (size_t)p3.x * 256 + lane * 8);
        float w0 = __int_as_float(p0.y), w1 = __int_as_float(p1.y);
        float w2 = __int_as_float(p2.y), w3 = __int_as_float(p3.y);
        float2 a0 = __half22float2(*(__half2*)&r0.x), b0 = __half22float2(*(__half2*)&r0.y);
        float2 a1 = __half22float2(*(__half2*)&r1.x), b1 = __half22float2(*(__half2*)&r1.y);
        float2 a2 = __half22float2(*(__half2*)&r2.x), b2 = __half22float2(*(__half2*)&r2.y);
        float2 a3 = __half22float2(*(__half2*)&r3.x), b3 = __half22float2(*(__half2*)&r3.y);
        acc.x = fmaf(w0, a0.x, acc.x); acc.y = fmaf(w0, a0.y, acc.y);
        acc.z = fmaf(w0, b0.x, acc.z); acc.w = fmaf(w0, b0.y, acc.w);
        acc.x = fmaf(w1, a1.x, acc.x); acc.y = fmaf(w1, a1.y, acc.y);
        acc.z = fmaf(w1, b1.x, acc.z); acc.w = fmaf(w1, b1.y, acc.w);
        acc.x = fmaf(w2, a2.x, acc.x); acc.y = fmaf(w2, a2.y, acc.y);
        acc.z = fmaf(w2, b2.x, acc.z); acc.w = fmaf(w2, b2.y, acc.w);
        acc.x = fmaf(w3, a3.x, acc.x); acc.y = fmaf(w3, a3.y, acc.y);
        acc.z = fmaf(w3, b3.x, acc.z); acc.w = fmaf(w3, b3.y, acc.w);
    }
    for (; i < end; i++) {
        int2 p0 = d_csw[i];
        float w0 = __int_as_float(p0.y);
        uint2 r0 = *(const uint2*)((const char*)h + (size_t)p0.x * 256 + lane * 8);
        float2 a0 = __half22float2(*(__half2*)&r0.x), b0 = __half22float2(*(__half2*)&r0.y);
        acc.x = fmaf(w0, a0.x, acc.x); acc.y = fmaf(w0, a0.y, acc.y);
        acc.z = fmaf(w0, b0.x, acc.z); acc.w = fmaf(w0, b0.y, acc.w);
    }
    float dv = d_dinv[w];
    {
        uint2 rs = *(const uint2*)((const char*)h + (size_t)w * 256 + lane * 8);
        float2 as = __half22float2(*(__half2*)&rs.x), bs = __half22float2(*(__half2*)&rs.y);
        acc.x = fmaf(dv, as.x, acc.x); acc.y = fmaf(dv, as.y, acc.y);
        acc.z = fmaf(dv, bs.x, acc.z); acc.w = fmaf(dv, bs.y, acc.w);
    }
    float4 bv = *(const float4*)(bias + lane * 4);
    float4 o;
    o.x = fmaxf(fmaf(dv, acc.x, bv.x), 0.f);
    o.y = fmaxf(fmaf(dv, acc.y, bv.y), 0.f);
    o.z = fmaxf(fmaf(dv, acc.z, bv.z), 0.f);
    o.w = fmaxf(fmaf(dv, acc.w, bv.w), 0.f);

    if (!FUSE_CLASSIFY) {
        *(float4*)(out + (size_t)w * 128 + lane * 4) = o;
    } else {
        // Classifier dot in-register: row element k = lane*4 + j maps to Wc[k*2 + c].
        float4 wa = *(const float4*)(Wc + 8 * lane);      // Wc[k,0],Wc[k,1],Wc[k+1,0],Wc[k+1,1]
        float4 wb = *(const float4*)(Wc + 8 * lane + 4);  // Wc[k+2,0],Wc[k+2,1],Wc[k+3,0],Wc[k+3,1]
        float p0 = o.x * wa.x + o.y * wa.z + o.z * wb.x + o.w * wb.z;
        float p1 = o.x * wa.y + o.y * wa.w + o.z * wb.y + o.w * wb.w;
#pragma unroll
        for (int off = 16; off; off >>= 1) {
            p0 += __shfl_xor_sync(0xffffffffu, p0, off);
            p1 += __shfl_xor_sync(0xffffffffu, p1, off);
        }
        if (lane == 0) {
            int g = d_batch32[w];
            atomicAdd(&d_gsum[2 * g], p0);
            atomicAdd(&d_gsum[2 * g + 1], p1);
        }
    }
}

// ---------------- finalize: mean + bias ----------------
__global__ void finalize_kernel(float* __restrict__ out, const float* __restrict__ bc, int G) {
    int i = blockIdx.x * blockDim.x + threadIdx.x;
    if (i < 2 * G) {
        int g = i >> 1, c = i & 1;
        float cnt = (float)d_gcnt[g];
        out[i] = d_gsum[i] / fmaxf(cnt, 1.f) + bc[c];
    }
}

// ---------------- launch ----------------
extern "C" void kernel_launch(void* const* d_in, const int* in_sizes, int n_in,
                              void* d_out, int out_size) {
    // Identify inputs by element count (robust to metadata ordering).
    const float* x = nullptr;
    const void* ei = nullptr;
    const void* batch = nullptr;
    const float *W1 = nullptr, *b1 = nullptr, *W2 = nullptr, *b2 = nullptr;
    const float *Wc = nullptr, *bc = nullptr;
    int x_elems = 0, ei_elems = 0;

    for (int i = 0; i < n_in; i++) {
        int s = in_sizes[i];
        const void* p = d_in[i];
        if (s >= 8000000)      { x = (const float*)p; x_elems = s; }
        else if (s >= 1000000) { ei = p; ei_elems = s; }
        else if (s == NN)      { batch = p; }
        else if (s == DH * DH) { if (!W1) W1 = (const float*)p; else W2 = (const float*)p; }
        else if (s == DH)      { if (!b1) b1 = (const float*)p; else b2 = (const float*)p; }
        else if (s == 2 * DH)  { Wc = (const float*)p; }
        else if (s == 2)       { bc = (const float*)p; }
    }

    float* out = (float*)d_out;
    int N = x_elems / DH;
    int E = ei_elems / 2;
    int G = out_size / 2;

    const int T = 256;
    int gemm_smem = 128 * 128 * 4 + BM * XS_PITCH * 4;
    cudaFuncSetAttribute(gemm128_kernel<0>, cudaFuncAttributeMaxDynamicSharedMemorySize, gemm_smem);
    cudaFuncSetAttribute(gemm128_kernel<2>, cudaFuncAttributeMaxDynamicSharedMemorySize, gemm_smem);

    int gemm_blocks = (N + BM - 1) / BM;
    int agg_blocks = (N + 7) / 8;
    int conv_blocks = (max(E, N) + T - 1) / T;

    // Build phase (4 launches)
    init_kernel<<<(N + T - 1) / T, T>>>(ei, 2 * E, N);                 // 0
    convert_kernel<<<conv_blocks, T>>>(ei, batch, E, N);               // 1
    scan_kernel<<<1, 1024>>>(N);                                       // 2 (+ dinv)
    fill_kernel<<<(E + T - 1) / T, T>>>(E);                            // 3

    // Layer 1
    gemm128_kernel<0><<<gemm_blocks, T, gemm_smem>>>(x, W1, N);        // 4
    agg_kernel<false><<<agg_blocks, T>>>(b1, nullptr, N);              // 5  <- ncu -s 5 target
    // Layer 2 (+ classifier fused into agg epilogue)
    gemm128_kernel<2><<<gemm_blocks, T, gemm_smem>>>(nullptr, W2, N);  // 6
    agg_kernel<true><<<agg_blocks, T>>>(b2, Wc, N);                    // 7

    finalize_kernel<<<(2 * G + T - 1) / T, T>>>(out, bc, G);           // 8
}